// round 15
// baseline (speedup 1.0000x reference)
#include <cuda_runtime.h>
#include <cuda_bf16.h>
#include <math.h>

#define NN 50000
#define NE 800000
#define NT 850000     // NE + NN self loops
#define NGRAPH 512
#define NCLS 120

#define MT1 391                  // ceil(NN/128)
#define GB1 (MT1 * 2)            // Ka tiles: 2 col-blocks of 128
#define CNTB 3125
#define NODB 196                 // ceil(NN/256)
#define GRID_A (GB1 + NODB)

#define SCAN_B   200
#define SCAN_SEG 250             // 200*250 == NN exactly

// ---------------- device scratch (no allocations allowed) ----------------
__device__ __align__(16) __nv_bfloat16 g_h1b[(size_t)NN * 256]; // layer1 feats (bf16)
__device__ __align__(16) __nv_bfloat16 g_h2b[(size_t)NN * 64];  // layer2 feats (bf16)
__device__ __align__(16) __nv_bfloat16 g_x2b[(size_t)NN * 256]; // elu(layer1 out), bf16
__device__ __align__(16) float g_als[NN * 4];   // layer1 logits (src)
__device__ __align__(16) float g_ald[NN * 4];   // layer1 logits (dst)
__device__ float g_als2[NN];                    // layer2 logits
__device__ float g_ald2[NN];
__device__ __align__(16) float g_w1[(size_t)NT * 4];   // layer1 edge weights
__device__ __align__(16) float g_v1s[256];      // W1 @ a_src1 per head [4][64]
__device__ __align__(16) float g_v1d[256];
__device__ __align__(16) float g_u2s[256];      // W2 @ a_src2
__device__ __align__(16) float g_u2d[256];
__device__ int   g_deg[NN];          // invariant: zero at entry (reset by scatterS)
__device__ int   g_starts[NN + 1];
__device__ int   g_rank[NE];
__device__ int   g_srcs[NT];
__device__ int   g_dst[NT];
__device__ float g_pool[NGRAPH * 64];  // invariant: zero at entry (reset by cls)
__device__ float g_cnt[NGRAPH];        // invariant: zero at entry (reset by cls)

// ---------------- helpers ----------------
#define FMA2(d, a, b) asm("fma.rn.f32x2 %0, %1, %2, %0;" : "+l"(d) : "l"(a), "l"(b))
#define PACK2(d, x)   asm("mov.b64 %0, {%1, %1};" : "=l"(d) : "f"(x))
#define UNPACK2(lo, hi, d) asm("mov.b64 {%0, %1}, %2;" : "=f"(lo), "=f"(hi) : "l"(d))
#define B2F2(dst, u) { unsigned _lo = (u) << 16, _hi = (u) & 0xffff0000u; \
    asm("mov.b64 %0, {%1, %2};" : "=l"(dst) : "r"(_lo), "r"(_hi)); }

__device__ __forceinline__ float lrelu(float v) { return v > 0.f ? v : 0.2f * v; }

__device__ __forceinline__ unsigned f2tf32(float f) {
    unsigned r;
    asm("cvt.rna.tf32.f32 %0, %1;" : "=r"(r) : "f"(f));
    return r;
}

#define MMA_TF32(d0, d1, d2, d3, a0, a1, a2, a3, b0, b1) \
    asm volatile("mma.sync.aligned.m16n8k8.row.col.f32.tf32.tf32.f32 " \
        "{%0,%1,%2,%3}, {%4,%5,%6,%7}, {%8,%9}, {%0,%1,%2,%3};" \
        : "+f"(d0), "+f"(d1), "+f"(d2), "+f"(d3) \
        : "r"(a0), "r"(a1), "r"(a2), "r"(a3), "r"(b0), "r"(b1))

// ---------------- tf32 tensor-core GEMM tile (features only; logits decoupled) --------
// 128-row M tile x NTILE cols. 8 warps: 4 row groups (32 rows) x 2 col groups.
// smem holds fragment-permuted tf32: A frag = LDS.128/lane, B frag = LDS.64/lane.
template<int KDIM, int NTILE, bool ABF16>
__device__ __forceinline__ void gemm_tf32_tile(
    const void* __restrict__ Araw, const float* __restrict__ B,
    __nv_bfloat16* __restrict__ Cb, int ldb, int row0, int col0)
{
    constexpr int NW  = NTILE / 16;    // n8 tiles per warp: 8 (Ka) / 4 (Kb)
    constexpr int NT8 = NTILE / 8;
    constexpr int NT4 = NTILE / 4;
    extern __shared__ __align__(16) unsigned smem_u[];
    unsigned* As = smem_u;             // 128x64 permuted
    unsigned* Bs = smem_u + 128 * 64;  // 64xNTILE permuted

    int tid = threadIdx.x;             // 256
    int warp = tid >> 5, lane = tid & 31;
    int rw = warp >> 1, cw = warp & 1;

    float d[2][NW][4];
#pragma unroll
    for (int mi = 0; mi < 2; mi++)
#pragma unroll
        for (int ni = 0; ni < NW; ni++)
#pragma unroll
            for (int q = 0; q < 4; q++) d[mi][ni][q] = 0.f;

    for (int k0 = 0; k0 < KDIM; k0 += 64) {
        // ---- A -> permuted smem ----
        if (!ABF16) {
            const float* A = (const float*)Araw;
#pragma unroll
            for (int it = 0; it < 8; it++) {
                int v = it * 256 + tid;
                int r = v >> 4, c4 = v & 15;
                int gr = row0 + r;
                float4 av = (gr < NN) ? *(const float4*)&A[(size_t)gr * KDIM + k0 + c4 * 4]
                                      : make_float4(0.f, 0.f, 0.f, 0.f);
                int cl = c4 * 4;
                int tile = ((r >> 4) << 3) + (cl >> 3);
                int reg  = ((r >> 3) & 1) | (((cl >> 2) & 1) << 1);
                unsigned* base = As + tile * 128 + ((r & 7) << 4) + reg;
                base[0]  = f2tf32(av.x);
                base[4]  = f2tf32(av.y);
                base[8]  = f2tf32(av.z);
                base[12] = f2tf32(av.w);
            }
        } else {
            const __nv_bfloat16* A = (const __nv_bfloat16*)Araw;
#pragma unroll
            for (int it = 0; it < 4; it++) {
                int v = it * 256 + tid;
                int r = v >> 3, c8 = v & 7;
                int gr = row0 + r;
                uint4 raw = (gr < NN) ? *(const uint4*)&A[(size_t)gr * KDIM + k0 + c8 * 8]
                                      : make_uint4(0u, 0u, 0u, 0u);
                // 8 bf16 -> f32 bits (exact tf32: bf16 mantissa subset)
                unsigned e0 = raw.x << 16, e1 = raw.x & 0xffff0000u;
                unsigned e2 = raw.y << 16, e3 = raw.y & 0xffff0000u;
                unsigned e4 = raw.z << 16, e5 = raw.z & 0xffff0000u;
                unsigned e6 = raw.w << 16, e7 = raw.w & 0xffff0000u;
                int tile = ((r >> 4) << 3) + c8;
                int rb = (r >> 3) & 1;
                unsigned* base = As + tile * 128 + ((r & 7) << 4);
                base[0 + rb]  = e0; base[4 + rb]  = e1;
                base[8 + rb]  = e2; base[12 + rb] = e3;
                base[0 + (rb | 2)]  = e4; base[4 + (rb | 2)]  = e5;
                base[8 + (rb | 2)]  = e6; base[12 + (rb | 2)] = e7;
            }
        }
        // ---- B -> permuted smem ----
#pragma unroll
        for (int it = 0; it < 64 * NT4 / 256; it++) {
            int v = it * 256 + tid;
            int r = v / NT4, c4 = v % NT4;
            float4 bv = *(const float4*)&B[(size_t)(k0 + r) * ldb + col0 + c4 * 4];
            int nl = c4 * 4;
            int tile = ((r >> 3) * NT8) + (nl >> 3);
            unsigned* base = Bs + tile * 64 + ((nl & 7) << 3) + ((r & 3) << 1) + ((r >> 2) & 1);
            base[0]  = f2tf32(bv.x);
            base[8]  = f2tf32(bv.y);
            base[16] = f2tf32(bv.z);
            base[24] = f2tf32(bv.w);
        }
        __syncthreads();
#pragma unroll
        for (int kt = 0; kt < 8; kt++) {
            unsigned af[2][4];
#pragma unroll
            for (int mi = 0; mi < 2; mi++) {
                uint4 t = *(const uint4*)&As[(((rw * 2 + mi) << 3) + kt) * 128 + (lane << 2)];
                af[mi][0] = t.x; af[mi][1] = t.y; af[mi][2] = t.z; af[mi][3] = t.w;
            }
            unsigned bf[NW][2];
#pragma unroll
            for (int ni = 0; ni < NW; ni++) {
                uint2 t = *(const uint2*)&Bs[(kt * NT8 + cw * NW + ni) * 64 + (lane << 1)];
                bf[ni][0] = t.x; bf[ni][1] = t.y;
            }
#pragma unroll
            for (int mi = 0; mi < 2; mi++)
#pragma unroll
                for (int ni = 0; ni < NW; ni++)
                    MMA_TF32(d[mi][ni][0], d[mi][ni][1], d[mi][ni][2], d[mi][ni][3],
                             af[mi][0], af[mi][1], af[mi][2], af[mi][3],
                             bf[ni][0], bf[ni][1]);
        }
        __syncthreads();
    }

    // epilogue: bf16 store. D frag: rows lane>>2, +8; cols 2*(lane&3), +1 per n8 tile.
#pragma unroll
    for (int mi = 0; mi < 2; mi++) {
        int rbase = row0 + rw * 32 + mi * 16 + (lane >> 2);
#pragma unroll
        for (int half = 0; half < 2; half++) {
            int gr = rbase + half * 8;
            if (gr < NN) {
#pragma unroll
                for (int ni = 0; ni < NW; ni++) {
                    int gc = col0 + cw * (NW * 8) + ni * 8 + 2 * (lane & 3);
                    __nv_bfloat162 p = __floats2bfloat162_rn(d[mi][ni][half * 2],
                                                             d[mi][ni][half * 2 + 1]);
                    *(__nv_bfloat162*)&Cb[(size_t)gr * ldb + gc] = p;
                }
            }
        }
    }
}

// ---------------- K_a: tf32 gemm1 || graph counts ----------------
__global__ void __launch_bounds__(256) Ka_kernel(
    const float* __restrict__ x, const float* __restrict__ W1,
    const int* __restrict__ batch)
{
    int b = blockIdx.x;
    if (b < GB1) {
        int row0 = (b >> 1) * 128;
        int col0 = (b & 1) * 128;
        gemm_tf32_tile<64, 128, false>(x, W1, g_h1b, 256, row0, col0);
    } else {
        int i = (b - GB1) * 256 + threadIdx.x;
        if (i < NN) atomicAdd(&g_cnt[batch[i]], 1.0f);
    }
}

__global__ void __launch_bounds__(256) Kb_kernel(const float* __restrict__ W2)
{
    gemm_tf32_tile<256, 64, true>(g_x2b, W2, g_h2b, 64, blockIdx.x * 128, 0);
}

// ---------------- vprep: projected attention vectors (fp32-exact logit path) ----------
__global__ void vprep_kernel(
    const float* __restrict__ W1, const float* __restrict__ as1, const float* __restrict__ ad1,
    const float* __restrict__ W2, const float* __restrict__ as2, const float* __restrict__ ad2)
{
    int t = threadIdx.x;               // 256
    int h = t >> 6, k = t & 63;
    float vs = 0.f, vd = 0.f;
#pragma unroll 8
    for (int dd = 0; dd < 64; dd++) {
        float w = W1[k * 256 + h * 64 + dd];
        vs += w * as1[h * 64 + dd];
        vd += w * ad1[h * 64 + dd];
    }
    g_v1s[h * 64 + k] = vs;
    g_v1d[h * 64 + k] = vd;
    float us = 0.f, ud = 0.f;
#pragma unroll 8
    for (int dd = 0; dd < 64; dd++) {
        float w = W2[t * 64 + dd];
        us += w * as2[dd];
        ud += w * ad2[dd];
    }
    g_u2s[t] = us;
    g_u2d[t] = ud;
}

// ---------------- attn1: layer-1 logits straight from x (warp per node) ----------------
__global__ void attn1_kernel(const float* __restrict__ x) {
    int warp = (blockIdx.x * blockDim.x + threadIdx.x) >> 5;
    int lane = threadIdx.x & 31;
    if (warp >= NN) return;
    float xa = x[(size_t)warp * 64 + lane];
    float xb = x[(size_t)warp * 64 + 32 + lane];
    float s[4], dd[4];
#pragma unroll
    for (int h = 0; h < 4; h++) {
        float ss = xa * g_v1s[h * 64 + lane] + xb * g_v1s[h * 64 + 32 + lane];
        float sd = xa * g_v1d[h * 64 + lane] + xb * g_v1d[h * 64 + 32 + lane];
#pragma unroll
        for (int o = 16; o; o >>= 1) {
            ss += __shfl_xor_sync(0xffffffffu, ss, o);
            sd += __shfl_xor_sync(0xffffffffu, sd, o);
        }
        s[h] = ss; dd[h] = sd;
    }
    if (lane == 0) {
        *(float4*)&g_als[warp * 4] = make_float4(s[0], s[1], s[2], s[3]);
        *(float4*)&g_ald[warp * 4] = make_float4(dd[0], dd[1], dd[2], dd[3]);
    }
}

// ---------------- side stream: CSR build ----------------
__global__ void hist_kernel(const int* __restrict__ ei) {
    int i = blockIdx.x * blockDim.x + threadIdx.x;
    if (i < NE) {
        int d = ei[NE + i];
        g_rank[i] = atomicAdd(&g_deg[d], 1);
    }
}

__device__ __forceinline__ int block_incl_scan256(int v) {
    __shared__ int wsum[8];
    int lane = threadIdx.x & 31, wid = threadIdx.x >> 5;
    int x = v;
#pragma unroll
    for (int o = 1; o < 32; o <<= 1) {
        int y = __shfl_up_sync(0xffffffffu, x, o);
        if (lane >= o) x += y;
    }
    if (lane == 31) wsum[wid] = x;
    __syncthreads();
    if (wid == 0 && lane < 8) {
        int w = wsum[lane];
#pragma unroll
        for (int o = 1; o < 8; o <<= 1) {
            int y = __shfl_up_sync(0x000000ffu, w, o);
            if (lane >= o) w += y;
        }
        wsum[lane] = w;
    }
    __syncthreads();
    if (wid > 0) x += wsum[wid - 1];
    return x;
}

__global__ void scan_kernel() {
    __shared__ int red[8];
    __shared__ int s_boff;
    int b = blockIdx.x, t = threadIdx.x, lane = t & 31, wid = t >> 5;
    int lim = b * SCAN_SEG;
    int partial = 0;
    for (int i = t; i < lim; i += 256) partial += g_deg[i];
#pragma unroll
    for (int o = 16; o; o >>= 1) partial += __shfl_xor_sync(0xffffffffu, partial, o);
    if (lane == 0) red[wid] = partial;
    __syncthreads();
    if (t == 0) {
        int s = 0;
#pragma unroll
        for (int k = 0; k < 8; k++) s += red[k];
        s_boff = s + lim;
    }
    __syncthreads();
    int boff = s_boff;

    int i = lim + t;
    int v = (t < SCAN_SEG) ? g_deg[i] + 1 : 0;
    int inc = block_incl_scan256(v);
    if (t < SCAN_SEG) g_starts[i] = inc - v + boff;
    if (b == SCAN_B - 1 && t == SCAN_SEG - 1) g_starts[NN] = inc + boff;
}

__global__ void scatterS_kernel(const int* __restrict__ ei) {
    int i = blockIdx.x * blockDim.x + threadIdx.x;
    if (i < NN) g_deg[i] = 0;        // reset invariant
    int s, d, slot;
    if (i < NE) {
        s = ei[i]; d = ei[NE + i];
        slot = g_starts[d] + g_rank[i];
    } else if (i < NT) {
        s = d = i - NE;
        slot = g_starts[d + 1] - 1;
    } else return;
    g_srcs[slot] = s;
    g_dst[slot] = d;
}

// scatterW: layer1 edge weights (needs als/ald from attn1 + srcs/dst)
__global__ void scatterW_kernel() {
    int i = blockIdx.x * blockDim.x + threadIdx.x;
    if (i >= NT) return;
    int s = g_srcs[i];
    int d = g_dst[i];
    float4 as = *(const float4*)&g_als[s * 4];
    float4 ad = *(const float4*)&g_ald[d * 4];
    float4 w;
    w.x = __expf(lrelu(as.x + ad.x));
    w.y = __expf(lrelu(as.y + ad.y));
    w.z = __expf(lrelu(as.z + ad.z));
    w.w = __expf(lrelu(as.w + ad.w));
    *(float4*)&g_w1[(size_t)i * 4] = w;
}

// ---------------- layer 1 aggregation + layer-2 logits in epilogue ----------------
__global__ void __launch_bounds__(64) agg1_kernel(const float* __restrict__ b1) {
    int warp = (blockIdx.x * blockDim.x + threadIdx.x) >> 5;
    int lane = threadIdx.x & 31;
    if (warp >= NN) return;
    int e0 = g_starts[warp], e1 = g_starts[warp + 1];

    int hq = lane >> 3;

    unsigned long long acc2[4] = {0ull, 0ull, 0ull, 0ull};
    float ssum = 0.f;
#pragma unroll 4
    for (int i = e0; i < e1; i++) {
        int s = g_srcs[i];                       // uniform -> broadcast
        float wq = g_w1[(size_t)i * 4 + hq];
        ssum += wq;
        unsigned long long w2; PACK2(w2, wq);
        uint4 hv = *(const uint4*)(g_h1b + (size_t)s * 256 + lane * 8);
        unsigned long long v0, v1, v2, v3;
        B2F2(v0, hv.x); B2F2(v1, hv.y); B2F2(v2, hv.z); B2F2(v3, hv.w);
        FMA2(acc2[0], w2, v0);
        FMA2(acc2[1], w2, v1);
        FMA2(acc2[2], w2, v2);
        FMA2(acc2[3], w2, v3);
    }
    float inv = 1.f / ssum;

    float acc[8];
#pragma unroll
    for (int q = 0; q < 4; q++) UNPACK2(acc[2 * q], acc[2 * q + 1], acc2[q]);

    float4 bva = *(const float4*)&b1[lane * 8];
    float4 bvb = *(const float4*)&b1[lane * 8 + 4];
    float bv[8] = {bva.x, bva.y, bva.z, bva.w, bvb.x, bvb.y, bvb.z, bvb.w};
    float o0[8];
#pragma unroll
    for (int j = 0; j < 8; j++) {
        float v = acc[j] * inv + bv[j];
        o0[j] = v > 0.f ? v : expm1f(v);         // ELU (fp32, pre-rounding)
    }

    // layer-2 logits from fp32 x2: al2 = x2 . (W2 @ a)
    float4 ua = *(const float4*)&g_u2s[lane * 8];
    float4 ub = *(const float4*)&g_u2s[lane * 8 + 4];
    float4 va = *(const float4*)&g_u2d[lane * 8];
    float4 vb = *(const float4*)&g_u2d[lane * 8 + 4];
    float us[8] = {ua.x, ua.y, ua.z, ua.w, ub.x, ub.y, ub.z, ub.w};
    float ud[8] = {va.x, va.y, va.z, va.w, vb.x, vb.y, vb.z, vb.w};
    float ss2 = 0.f, sd2 = 0.f;
#pragma unroll
    for (int j = 0; j < 8; j++) { ss2 += o0[j] * us[j]; sd2 += o0[j] * ud[j]; }
#pragma unroll
    for (int o = 16; o; o >>= 1) {
        ss2 += __shfl_xor_sync(0xffffffffu, ss2, o);
        sd2 += __shfl_xor_sync(0xffffffffu, sd2, o);
    }
    if (lane == 0) { g_als2[warp] = ss2; g_ald2[warp] = sd2; }

    unsigned pk[4];
#pragma unroll
    for (int q = 0; q < 4; q++) {
        __nv_bfloat162 p = __floats2bfloat162_rn(o0[2 * q], o0[2 * q + 1]);
        pk[q] = *(unsigned*)&p;
    }
    *(uint4*)(g_x2b + (size_t)warp * 256 + lane * 8) =
        make_uint4(pk[0], pk[1], pk[2], pk[3]);
}

// ---------------- layer 2 aggregation + fused global mean pool ----------------
__global__ void __launch_bounds__(64) agg2_kernel(const float* __restrict__ b2,
                                                  const int* __restrict__ batch) {
    int warp = (blockIdx.x * blockDim.x + threadIdx.x) >> 5;
    int lane = threadIdx.x & 31;
    if (warp >= NN) return;
    int e0 = g_starts[warp], e1 = g_starts[warp + 1];
    float ad = g_ald2[warp];

    float a0 = 0.f, a1 = 0.f, ssum = 0.f;
#pragma unroll 4
    for (int i = e0; i < e1; i++) {
        int s = g_srcs[i];
        float w = __expf(lrelu(g_als2[s] + ad));
        ssum += w;
        unsigned hv = *(const unsigned*)(g_h2b + (size_t)s * 64 + lane * 2);
        float fx = __uint_as_float(hv << 16);
        float fy = __uint_as_float(hv & 0xffff0000u);
        a0 += w * fx; a1 += w * fy;
    }
    float inv = 1.f / ssum;
    int g = batch[warp];
    atomicAdd(&g_pool[g * 64 + lane * 2],     a0 * inv + b2[lane * 2]);
    atomicAdd(&g_pool[g * 64 + lane * 2 + 1], a1 * inv + b2[lane * 2 + 1]);
}

// ---------------- classifier (reads then resets pool/cnt) ----------------
__global__ void cls_kernel(const float* __restrict__ Wc,
                           const float* __restrict__ bc,
                           float* __restrict__ out) {
    int g = blockIdx.x;
    __shared__ float emb[64];
    float c = fmaxf(g_cnt[g], 1.f);
    if (threadIdx.x < 64) emb[threadIdx.x] = g_pool[g * 64 + threadIdx.x] / c;
    __syncthreads();
    if (threadIdx.x < 64) g_pool[g * 64 + threadIdx.x] = 0.f;
    if (threadIdx.x == 64) g_cnt[g] = 0.f;
    int cc = threadIdx.x;
    if (cc < NCLS) {
        float s = bc[cc];
#pragma unroll 16
        for (int d = 0; d < 64; d++) s += emb[d] * Wc[d * NCLS + cc];
        out[g * NCLS + cc] = s;
    }
}

// ---------------- launch ----------------
#define SMEM_KA ((128 * 64 + 64 * 128) * 4)   // 65536
#define SMEM_KB ((128 * 64 + 64 * 64) * 4)    // 49152

extern "C" void kernel_launch(void* const* d_in, const int* in_sizes, int n_in,
                              void* d_out, int out_size) {
    const float* x      = (const float*)d_in[0];
    const float* W1     = (const float*)d_in[1];
    const float* a_src1 = (const float*)d_in[2];
    const float* a_dst1 = (const float*)d_in[3];
    const float* b1     = (const float*)d_in[4];
    const float* W2     = (const float*)d_in[5];
    const float* a_src2 = (const float*)d_in[6];
    const float* a_dst2 = (const float*)d_in[7];
    const float* b2     = (const float*)d_in[8];
    const float* Wc     = (const float*)d_in[9];
    const float* bc     = (const float*)d_in[10];
    const int* ei       = (const int*)d_in[11];
    const int* batch    = (const int*)d_in[12];
    float* out = (float*)d_out;

    static cudaStream_t s2 = nullptr;
    static cudaEvent_t evFork = nullptr, evAttn = nullptr, evJoin = nullptr;
    if (!s2) {
        cudaStreamCreateWithFlags(&s2, cudaStreamNonBlocking);
        cudaEventCreateWithFlags(&evFork, cudaEventDisableTiming);
        cudaEventCreateWithFlags(&evAttn, cudaEventDisableTiming);
        cudaEventCreateWithFlags(&evJoin, cudaEventDisableTiming);
    }

    cudaFuncSetAttribute(Ka_kernel, cudaFuncAttributeMaxDynamicSharedMemorySize, SMEM_KA);
    cudaFuncSetAttribute(Kb_kernel, cudaFuncAttributeMaxDynamicSharedMemorySize, SMEM_KB);

    // fork: CSR build on s2
    cudaEventRecord(evFork, 0);
    cudaStreamWaitEvent(s2, evFork, 0);
    hist_kernel<<<CNTB, 256, 0, s2>>>(ei);
    scan_kernel<<<SCAN_B, 256, 0, s2>>>();
    scatterS_kernel<<<(NT + 255) / 256, 256, 0, s2>>>(ei);

    // main: logit path then GEMM
    vprep_kernel<<<1, 256>>>(W1, a_src1, a_dst1, W2, a_src2, a_dst2);
    attn1_kernel<<<(NN * 32 + 255) / 256, 256>>>(x);
    cudaEventRecord(evAttn, 0);

    // s2: weights once logits + CSR ready (hidden under Ka)
    cudaStreamWaitEvent(s2, evAttn, 0);
    scatterW_kernel<<<(NT + 255) / 256, 256, 0, s2>>>();
    cudaEventRecord(evJoin, s2);

    Ka_kernel<<<GRID_A, 256, SMEM_KA>>>(x, W1, batch);

    cudaStreamWaitEvent(0, evJoin, 0);
    agg1_kernel<<<(NN * 32 + 63) / 64, 64>>>(b1);
    Kb_kernel<<<MT1, 256, SMEM_KB>>>(W2);
    agg2_kernel<<<(NN * 32 + 63) / 64, 64>>>(b2, batch);
    cls_kernel<<<NGRAPH, 128>>>(Wc, bc, out);
}

// round 17
// speedup vs baseline: 1.0515x; 1.0515x over previous
#include <cuda_runtime.h>
#include <cuda_bf16.h>
#include <math.h>

#define NN 50000
#define NE 800000
#define NT 850000     // NE + NN self loops
#define NGRAPH 512
#define NCLS 120

#define MT1 391                  // ceil(NN/128)
#define GB1 (MT1 * 2)            // Ka tiles: 2 col-blocks of 128
#define CNTB 3125
#define NODB 196                 // ceil(NN/256)
#define GRID_A (GB1 + NODB)

#define SCAN_B   200
#define SCAN_SEG 250             // 200*250 == NN exactly

// ---------------- device scratch (no allocations allowed) ----------------
__device__ __align__(16) __nv_bfloat16 g_h1b[(size_t)NN * 256]; // layer1 feats (bf16)
__device__ __align__(16) __nv_bfloat16 g_h2b[(size_t)NN * 64];  // layer2 feats (bf16)
__device__ __align__(16) __nv_bfloat16 g_x2b[(size_t)NN * 256]; // elu(layer1 out), bf16
__device__ __align__(16) float g_als[NN * 4];   // layer1 logits (src)
__device__ __align__(16) float g_ald[NN * 4];   // layer1 logits (dst)
__device__ float g_als2[NN];                    // layer2 logits
__device__ float g_ald2[NN];
__device__ __align__(16) float g_w1[(size_t)NT * 4];   // layer1 edge weights
__device__ __align__(16) float g_v1s[256];      // W1 @ a_src1 per head [4][64]
__device__ __align__(16) float g_v1d[256];
__device__ __align__(16) float g_u2s[256];      // W2 @ a_src2
__device__ __align__(16) float g_u2d[256];
__device__ int   g_deg[NN];          // invariant: zero at entry (reset by scatterS)
__device__ int   g_starts[NN + 1];
__device__ int   g_rank[NE];
__device__ int   g_srcs[NT];
__device__ int   g_dst[NT];
__device__ float g_pool[NGRAPH * 64];  // invariant: zero at entry (reset by cls)
__device__ float g_cnt[NGRAPH];        // invariant: zero at entry (reset by cls)

// ---------------- helpers ----------------
#define FMA2(d, a, b) asm("fma.rn.f32x2 %0, %1, %2, %0;" : "+l"(d) : "l"(a), "l"(b))
#define PACK2(d, x)   asm("mov.b64 %0, {%1, %1};" : "=l"(d) : "f"(x))
#define UNPACK2(lo, hi, d) asm("mov.b64 {%0, %1}, %2;" : "=f"(lo), "=f"(hi) : "l"(d))
#define B2F2(dst, u) { unsigned _lo = (u) << 16, _hi = (u) & 0xffff0000u; \
    asm("mov.b64 %0, {%1, %2};" : "=l"(dst) : "r"(_lo), "r"(_hi)); }

__device__ __forceinline__ float lrelu(float v) { return v > 0.f ? v : 0.2f * v; }

__device__ __forceinline__ unsigned f2tf32(float f) {
    unsigned r;
    asm("cvt.rna.tf32.f32 %0, %1;" : "=r"(r) : "f"(f));
    return r;
}

#define MMA_TF32(d0, d1, d2, d3, a0, a1, a2, a3, b0, b1) \
    asm volatile("mma.sync.aligned.m16n8k8.row.col.f32.tf32.tf32.f32 " \
        "{%0,%1,%2,%3}, {%4,%5,%6,%7}, {%8,%9}, {%0,%1,%2,%3};" \
        : "+f"(d0), "+f"(d1), "+f"(d2), "+f"(d3) \
        : "r"(a0), "r"(a1), "r"(a2), "r"(a3), "r"(b0), "r"(b1))

// ---------------- tf32 tensor-core GEMM tile (features only; logits decoupled) --------
// (verified round 15: rel_err 4.0e-4)
template<int KDIM, int NTILE, bool ABF16>
__device__ __forceinline__ void gemm_tf32_tile(
    const void* __restrict__ Araw, const float* __restrict__ B,
    __nv_bfloat16* __restrict__ Cb, int ldb, int row0, int col0)
{
    constexpr int NW  = NTILE / 16;
    constexpr int NT8 = NTILE / 8;
    constexpr int NT4 = NTILE / 4;
    extern __shared__ __align__(16) unsigned smem_u[];
    unsigned* As = smem_u;             // 128x64 permuted
    unsigned* Bs = smem_u + 128 * 64;  // 64xNTILE permuted

    int tid = threadIdx.x;             // 256
    int warp = tid >> 5, lane = tid & 31;
    int rw = warp >> 1, cw = warp & 1;

    float d[2][NW][4];
#pragma unroll
    for (int mi = 0; mi < 2; mi++)
#pragma unroll
        for (int ni = 0; ni < NW; ni++)
#pragma unroll
            for (int q = 0; q < 4; q++) d[mi][ni][q] = 0.f;

    for (int k0 = 0; k0 < KDIM; k0 += 64) {
        if (!ABF16) {
            const float* A = (const float*)Araw;
#pragma unroll
            for (int it = 0; it < 8; it++) {
                int v = it * 256 + tid;
                int r = v >> 4, c4 = v & 15;
                int gr = row0 + r;
                float4 av = (gr < NN) ? *(const float4*)&A[(size_t)gr * KDIM + k0 + c4 * 4]
                                      : make_float4(0.f, 0.f, 0.f, 0.f);
                int cl = c4 * 4;
                int tile = ((r >> 4) << 3) + (cl >> 3);
                int reg  = ((r >> 3) & 1) | (((cl >> 2) & 1) << 1);
                unsigned* base = As + tile * 128 + ((r & 7) << 4) + reg;
                base[0]  = f2tf32(av.x);
                base[4]  = f2tf32(av.y);
                base[8]  = f2tf32(av.z);
                base[12] = f2tf32(av.w);
            }
        } else {
            const __nv_bfloat16* A = (const __nv_bfloat16*)Araw;
#pragma unroll
            for (int it = 0; it < 4; it++) {
                int v = it * 256 + tid;
                int r = v >> 3, c8 = v & 7;
                int gr = row0 + r;
                uint4 raw = (gr < NN) ? *(const uint4*)&A[(size_t)gr * KDIM + k0 + c8 * 8]
                                      : make_uint4(0u, 0u, 0u, 0u);
                unsigned e0 = raw.x << 16, e1 = raw.x & 0xffff0000u;
                unsigned e2 = raw.y << 16, e3 = raw.y & 0xffff0000u;
                unsigned e4 = raw.z << 16, e5 = raw.z & 0xffff0000u;
                unsigned e6 = raw.w << 16, e7 = raw.w & 0xffff0000u;
                int tile = ((r >> 4) << 3) + c8;
                int rb = (r >> 3) & 1;
                unsigned* base = As + tile * 128 + ((r & 7) << 4);
                base[0 + rb]  = e0; base[4 + rb]  = e1;
                base[8 + rb]  = e2; base[12 + rb] = e3;
                base[0 + (rb | 2)]  = e4; base[4 + (rb | 2)]  = e5;
                base[8 + (rb | 2)]  = e6; base[12 + (rb | 2)] = e7;
            }
        }
#pragma unroll
        for (int it = 0; it < 64 * NT4 / 256; it++) {
            int v = it * 256 + tid;
            int r = v / NT4, c4 = v % NT4;
            float4 bv = *(const float4*)&B[(size_t)(k0 + r) * ldb + col0 + c4 * 4];
            int nl = c4 * 4;
            int tile = ((r >> 3) * NT8) + (nl >> 3);
            unsigned* base = Bs + tile * 64 + ((nl & 7) << 3) + ((r & 3) << 1) + ((r >> 2) & 1);
            base[0]  = f2tf32(bv.x);
            base[8]  = f2tf32(bv.y);
            base[16] = f2tf32(bv.z);
            base[24] = f2tf32(bv.w);
        }
        __syncthreads();
#pragma unroll
        for (int kt = 0; kt < 8; kt++) {
            unsigned af[2][4];
#pragma unroll
            for (int mi = 0; mi < 2; mi++) {
                uint4 t = *(const uint4*)&As[(((rw * 2 + mi) << 3) + kt) * 128 + (lane << 2)];
                af[mi][0] = t.x; af[mi][1] = t.y; af[mi][2] = t.z; af[mi][3] = t.w;
            }
            unsigned bf[NW][2];
#pragma unroll
            for (int ni = 0; ni < NW; ni++) {
                uint2 t = *(const uint2*)&Bs[(kt * NT8 + cw * NW + ni) * 64 + (lane << 1)];
                bf[ni][0] = t.x; bf[ni][1] = t.y;
            }
#pragma unroll
            for (int mi = 0; mi < 2; mi++)
#pragma unroll
                for (int ni = 0; ni < NW; ni++)
                    MMA_TF32(d[mi][ni][0], d[mi][ni][1], d[mi][ni][2], d[mi][ni][3],
                             af[mi][0], af[mi][1], af[mi][2], af[mi][3],
                             bf[ni][0], bf[ni][1]);
        }
        __syncthreads();
    }

#pragma unroll
    for (int mi = 0; mi < 2; mi++) {
        int rbase = row0 + rw * 32 + mi * 16 + (lane >> 2);
#pragma unroll
        for (int half = 0; half < 2; half++) {
            int gr = rbase + half * 8;
            if (gr < NN) {
#pragma unroll
                for (int ni = 0; ni < NW; ni++) {
                    int gc = col0 + cw * (NW * 8) + ni * 8 + 2 * (lane & 3);
                    __nv_bfloat162 p = __floats2bfloat162_rn(d[mi][ni][half * 2],
                                                             d[mi][ni][half * 2 + 1]);
                    *(__nv_bfloat162*)&Cb[(size_t)gr * ldb + gc] = p;
                }
            }
        }
    }
}

// ---------------- K_a: tf32 gemm1 || graph counts ----------------
__global__ void __launch_bounds__(256) Ka_kernel(
    const float* __restrict__ x, const float* __restrict__ W1,
    const int* __restrict__ batch)
{
    int b = blockIdx.x;
    if (b < GB1) {
        int row0 = (b >> 1) * 128;
        int col0 = (b & 1) * 128;
        gemm_tf32_tile<64, 128, false>(x, W1, g_h1b, 256, row0, col0);
    } else {
        int i = (b - GB1) * 256 + threadIdx.x;
        if (i < NN) atomicAdd(&g_cnt[batch[i]], 1.0f);
    }
}

__global__ void __launch_bounds__(256) Kb_kernel(const float* __restrict__ W2)
{
    gemm_tf32_tile<256, 64, true>(g_x2b, W2, g_h2b, 64, blockIdx.x * 128, 0);
}

// ---------------- vprep: warp-per-output (512 dot products of length 64) ----------
__global__ void __launch_bounds__(256) vprep_kernel(
    const float* __restrict__ W1, const float* __restrict__ as1, const float* __restrict__ ad1,
    const float* __restrict__ W2, const float* __restrict__ as2, const float* __restrict__ ad2)
{
    int w = (blockIdx.x * blockDim.x + threadIdx.x) >> 5;   // 0..511
    int lane = threadIdx.x & 31;
    if (w < 256) {
        int h = w >> 6, k = w & 63;
        const float* wr = &W1[k * 256 + h * 64];
        float vs = wr[lane] * as1[h * 64 + lane] + wr[32 + lane] * as1[h * 64 + 32 + lane];
        float vd = wr[lane] * ad1[h * 64 + lane] + wr[32 + lane] * ad1[h * 64 + 32 + lane];
#pragma unroll
        for (int o = 16; o; o >>= 1) {
            vs += __shfl_xor_sync(0xffffffffu, vs, o);
            vd += __shfl_xor_sync(0xffffffffu, vd, o);
        }
        if (lane == 0) { g_v1s[h * 64 + k] = vs; g_v1d[h * 64 + k] = vd; }
    } else {
        int t = w - 256;
        const float* wr = &W2[t * 64];
        float us = wr[lane] * as2[lane] + wr[32 + lane] * as2[32 + lane];
        float ud = wr[lane] * ad2[lane] + wr[32 + lane] * ad2[32 + lane];
#pragma unroll
        for (int o = 16; o; o >>= 1) {
            us += __shfl_xor_sync(0xffffffffu, us, o);
            ud += __shfl_xor_sync(0xffffffffu, ud, o);
        }
        if (lane == 0) { g_u2s[t] = us; g_u2d[t] = ud; }
    }
}

// ---------------- attn1: layer-1 logits straight from x (warp per node) ----------------
__global__ void attn1_kernel(const float* __restrict__ x) {
    int warp = (blockIdx.x * blockDim.x + threadIdx.x) >> 5;
    int lane = threadIdx.x & 31;
    if (warp >= NN) return;
    float xa = x[(size_t)warp * 64 + lane];
    float xb = x[(size_t)warp * 64 + 32 + lane];
    float s[4], dd[4];
#pragma unroll
    for (int h = 0; h < 4; h++) {
        float ss = xa * g_v1s[h * 64 + lane] + xb * g_v1s[h * 64 + 32 + lane];
        float sd = xa * g_v1d[h * 64 + lane] + xb * g_v1d[h * 64 + 32 + lane];
#pragma unroll
        for (int o = 16; o; o >>= 1) {
            ss += __shfl_xor_sync(0xffffffffu, ss, o);
            sd += __shfl_xor_sync(0xffffffffu, sd, o);
        }
        s[h] = ss; dd[h] = sd;
    }
    if (lane == 0) {
        *(float4*)&g_als[warp * 4] = make_float4(s[0], s[1], s[2], s[3]);
        *(float4*)&g_ald[warp * 4] = make_float4(dd[0], dd[1], dd[2], dd[3]);
    }
}

// ---------------- side stream: CSR build ----------------
__global__ void hist_kernel(const int* __restrict__ ei) {
    int i = blockIdx.x * blockDim.x + threadIdx.x;
    if (i < NE) {
        int d = ei[NE + i];
        g_rank[i] = atomicAdd(&g_deg[d], 1);
    }
}

__device__ __forceinline__ int block_incl_scan256(int v) {
    __shared__ int wsum[8];
    int lane = threadIdx.x & 31, wid = threadIdx.x >> 5;
    int x = v;
#pragma unroll
    for (int o = 1; o < 32; o <<= 1) {
        int y = __shfl_up_sync(0xffffffffu, x, o);
        if (lane >= o) x += y;
    }
    if (lane == 31) wsum[wid] = x;
    __syncthreads();
    if (wid == 0 && lane < 8) {
        int w = wsum[lane];
#pragma unroll
        for (int o = 1; o < 8; o <<= 1) {
            int y = __shfl_up_sync(0x000000ffu, w, o);
            if (lane >= o) w += y;
        }
        wsum[lane] = w;
    }
    __syncthreads();
    if (wid > 0) x += wsum[wid - 1];
    return x;
}

__global__ void scan_kernel() {
    __shared__ int red[8];
    __shared__ int s_boff;
    int b = blockIdx.x, t = threadIdx.x, lane = t & 31, wid = t >> 5;
    int lim = b * SCAN_SEG;
    int partial = 0;
    for (int i = t; i < lim; i += 256) partial += g_deg[i];
#pragma unroll
    for (int o = 16; o; o >>= 1) partial += __shfl_xor_sync(0xffffffffu, partial, o);
    if (lane == 0) red[wid] = partial;
    __syncthreads();
    if (t == 0) {
        int s = 0;
#pragma unroll
        for (int k = 0; k < 8; k++) s += red[k];
        s_boff = s + lim;
    }
    __syncthreads();
    int boff = s_boff;

    int i = lim + t;
    int v = (t < SCAN_SEG) ? g_deg[i] + 1 : 0;
    int inc = block_incl_scan256(v);
    if (t < SCAN_SEG) g_starts[i] = inc - v + boff;
    if (b == SCAN_B - 1 && t == SCAN_SEG - 1) g_starts[NN] = inc + boff;
}

__global__ void scatterS_kernel(const int* __restrict__ ei) {
    int i = blockIdx.x * blockDim.x + threadIdx.x;
    if (i < NN) g_deg[i] = 0;        // reset invariant
    int s, d, slot;
    if (i < NE) {
        s = ei[i]; d = ei[NE + i];
        slot = g_starts[d] + g_rank[i];
    } else if (i < NT) {
        s = d = i - NE;
        slot = g_starts[d + 1] - 1;
    } else return;
    g_srcs[slot] = s;
    g_dst[slot] = d;
}

// scatterW: layer1 edge weights (needs als/ald from attn1 + srcs/dst from scatterS)
__global__ void scatterW_kernel() {
    int i = blockIdx.x * blockDim.x + threadIdx.x;
    if (i >= NT) return;
    int s = g_srcs[i];
    int d = g_dst[i];
    float4 as = *(const float4*)&g_als[s * 4];
    float4 ad = *(const float4*)&g_ald[d * 4];
    float4 w;
    w.x = __expf(lrelu(as.x + ad.x));
    w.y = __expf(lrelu(as.y + ad.y));
    w.z = __expf(lrelu(as.z + ad.z));
    w.w = __expf(lrelu(as.w + ad.w));
    *(float4*)&g_w1[(size_t)i * 4] = w;
}

// ---------------- layer 1 aggregation + layer-2 logits in epilogue ----------------
__global__ void __launch_bounds__(64) agg1_kernel(const float* __restrict__ b1) {
    int warp = (blockIdx.x * blockDim.x + threadIdx.x) >> 5;
    int lane = threadIdx.x & 31;
    if (warp >= NN) return;
    int e0 = g_starts[warp], e1 = g_starts[warp + 1];

    int hq = lane >> 3;

    unsigned long long acc2[4] = {0ull, 0ull, 0ull, 0ull};
    float ssum = 0.f;
#pragma unroll 4
    for (int i = e0; i < e1; i++) {
        int s = g_srcs[i];                       // uniform -> broadcast
        float wq = g_w1[(size_t)i * 4 + hq];
        ssum += wq;
        unsigned long long w2; PACK2(w2, wq);
        uint4 hv = *(const uint4*)(g_h1b + (size_t)s * 256 + lane * 8);
        unsigned long long v0, v1, v2, v3;
        B2F2(v0, hv.x); B2F2(v1, hv.y); B2F2(v2, hv.z); B2F2(v3, hv.w);
        FMA2(acc2[0], w2, v0);
        FMA2(acc2[1], w2, v1);
        FMA2(acc2[2], w2, v2);
        FMA2(acc2[3], w2, v3);
    }
    float inv = 1.f / ssum;

    float acc[8];
#pragma unroll
    for (int q = 0; q < 4; q++) UNPACK2(acc[2 * q], acc[2 * q + 1], acc2[q]);

    float4 bva = *(const float4*)&b1[lane * 8];
    float4 bvb = *(const float4*)&b1[lane * 8 + 4];
    float bv[8] = {bva.x, bva.y, bva.z, bva.w, bvb.x, bvb.y, bvb.z, bvb.w};
    float o0[8];
#pragma unroll
    for (int j = 0; j < 8; j++) {
        float v = acc[j] * inv + bv[j];
        o0[j] = v > 0.f ? v : expm1f(v);         // ELU (fp32, pre-rounding)
    }

    // layer-2 logits from fp32 x2: al2 = x2 . (W2 @ a)
    float4 ua = *(const float4*)&g_u2s[lane * 8];
    float4 ub = *(const float4*)&g_u2s[lane * 8 + 4];
    float4 va = *(const float4*)&g_u2d[lane * 8];
    float4 vb = *(const float4*)&g_u2d[lane * 8 + 4];
    float us[8] = {ua.x, ua.y, ua.z, ua.w, ub.x, ub.y, ub.z, ub.w};
    float ud[8] = {va.x, va.y, va.z, va.w, vb.x, vb.y, vb.z, vb.w};
    float ss2 = 0.f, sd2 = 0.f;
#pragma unroll
    for (int j = 0; j < 8; j++) { ss2 += o0[j] * us[j]; sd2 += o0[j] * ud[j]; }
#pragma unroll
    for (int o = 16; o; o >>= 1) {
        ss2 += __shfl_xor_sync(0xffffffffu, ss2, o);
        sd2 += __shfl_xor_sync(0xffffffffu, sd2, o);
    }
    if (lane == 0) { g_als2[warp] = ss2; g_ald2[warp] = sd2; }

    unsigned pk[4];
#pragma unroll
    for (int q = 0; q < 4; q++) {
        __nv_bfloat162 p = __floats2bfloat162_rn(o0[2 * q], o0[2 * q + 1]);
        pk[q] = *(unsigned*)&p;
    }
    *(uint4*)(g_x2b + (size_t)warp * 256 + lane * 8) =
        make_uint4(pk[0], pk[1], pk[2], pk[3]);
}

// ---------------- layer 2 aggregation + fused global mean pool ----------------
__global__ void __launch_bounds__(64) agg2_kernel(const float* __restrict__ b2,
                                                  const int* __restrict__ batch) {
    int warp = (blockIdx.x * blockDim.x + threadIdx.x) >> 5;
    int lane = threadIdx.x & 31;
    if (warp >= NN) return;
    int e0 = g_starts[warp], e1 = g_starts[warp + 1];
    float ad = g_ald2[warp];

    float a0 = 0.f, a1 = 0.f, ssum = 0.f;
#pragma unroll 4
    for (int i = e0; i < e1; i++) {
        int s = g_srcs[i];
        float w = __expf(lrelu(g_als2[s] + ad));
        ssum += w;
        unsigned hv = *(const unsigned*)(g_h2b + (size_t)s * 64 + lane * 2);
        float fx = __uint_as_float(hv << 16);
        float fy = __uint_as_float(hv & 0xffff0000u);
        a0 += w * fx; a1 += w * fy;
    }
    float inv = 1.f / ssum;
    int g = batch[warp];
    atomicAdd(&g_pool[g * 64 + lane * 2],     a0 * inv + b2[lane * 2]);
    atomicAdd(&g_pool[g * 64 + lane * 2 + 1], a1 * inv + b2[lane * 2 + 1]);
}

// ---------------- classifier (reads then resets pool/cnt) ----------------
__global__ void cls_kernel(const float* __restrict__ Wc,
                           const float* __restrict__ bc,
                           float* __restrict__ out) {
    int g = blockIdx.x;
    __shared__ float emb[64];
    float c = fmaxf(g_cnt[g], 1.f);
    if (threadIdx.x < 64) emb[threadIdx.x] = g_pool[g * 64 + threadIdx.x] / c;
    __syncthreads();
    if (threadIdx.x < 64) g_pool[g * 64 + threadIdx.x] = 0.f;
    if (threadIdx.x == 64) g_cnt[g] = 0.f;
    int cc = threadIdx.x;
    if (cc < NCLS) {
        float s = bc[cc];
#pragma unroll 16
        for (int d = 0; d < 64; d++) s += emb[d] * Wc[d * NCLS + cc];
        out[g * NCLS + cc] = s;
    }
}

// ---------------- launch ----------------
#define SMEM_KA ((128 * 64 + 64 * 128) * 4)   // 65536
#define SMEM_KB ((128 * 64 + 64 * 64) * 4)    // 49152

extern "C" void kernel_launch(void* const* d_in, const int* in_sizes, int n_in,
                              void* d_out, int out_size) {
    const float* x      = (const float*)d_in[0];
    const float* W1     = (const float*)d_in[1];
    const float* a_src1 = (const float*)d_in[2];
    const float* a_dst1 = (const float*)d_in[3];
    const float* b1     = (const float*)d_in[4];
    const float* W2     = (const float*)d_in[5];
    const float* a_src2 = (const float*)d_in[6];
    const float* a_dst2 = (const float*)d_in[7];
    const float* b2     = (const float*)d_in[8];
    const float* Wc     = (const float*)d_in[9];
    const float* bc     = (const float*)d_in[10];
    const int* ei       = (const int*)d_in[11];
    const int* batch    = (const int*)d_in[12];
    float* out = (float*)d_out;

    static cudaStream_t s2 = nullptr, s3 = nullptr;
    static cudaEvent_t evFork = nullptr, evS = nullptr, evJoin = nullptr;
    if (!s2) {
        cudaStreamCreateWithFlags(&s2, cudaStreamNonBlocking);
        cudaStreamCreateWithFlags(&s3, cudaStreamNonBlocking);
        cudaEventCreateWithFlags(&evFork, cudaEventDisableTiming);
        cudaEventCreateWithFlags(&evS, cudaEventDisableTiming);
        cudaEventCreateWithFlags(&evJoin, cudaEventDisableTiming);
    }

    cudaFuncSetAttribute(Ka_kernel, cudaFuncAttributeMaxDynamicSharedMemorySize, SMEM_KA);
    cudaFuncSetAttribute(Kb_kernel, cudaFuncAttributeMaxDynamicSharedMemorySize, SMEM_KB);

    // fork
    cudaEventRecord(evFork, 0);
    cudaStreamWaitEvent(s2, evFork, 0);
    cudaStreamWaitEvent(s3, evFork, 0);

    // s2: CSR build
    hist_kernel<<<CNTB, 256, 0, s2>>>(ei);
    scan_kernel<<<SCAN_B, 256, 0, s2>>>();
    scatterS_kernel<<<(NT + 255) / 256, 256, 0, s2>>>(ei);
    cudaEventRecord(evS, s2);

    // s3: logit path, then edge weights (needs scatterS)
    vprep_kernel<<<64, 256, 0, s3>>>(W1, a_src1, a_dst1, W2, a_src2, a_dst2);
    attn1_kernel<<<(NN * 32 + 255) / 256, 256, 0, s3>>>(x);
    cudaStreamWaitEvent(s3, evS, 0);
    scatterW_kernel<<<(NT + 255) / 256, 256, 0, s3>>>();
    cudaEventRecord(evJoin, s3);

    // main: feature GEMM concurrent with all of the above
    Ka_kernel<<<GRID_A, 256, SMEM_KA>>>(x, W1, batch);

    cudaStreamWaitEvent(0, evJoin, 0);
    agg1_kernel<<<(NN * 32 + 63) / 64, 64>>>(b1);
    Kb_kernel<<<MT1, 256, SMEM_KB>>>(W2);
    agg2_kernel<<<(NN * 32 + 63) / 64, 64>>>(b2, batch);
    cls_kernel<<<NGRAPH, 128>>>(Wc, bc, out);
}